// round 5
// baseline (speedup 1.0000x reference)
#include <cuda_runtime.h>

// FusedMultiPool: out[b,s,h,w] = max_k x[b, idx[s,k], h, w]
// Shapes: x[32,256,64,64] f32, idx[128,8] i32, out[32,128,64,64] f32.
//
// Strategy: CTA = (batch b, 32-element hw strip). Stage all 256 channels for
// the strip into smem (coalesced, each x element read from DRAM exactly once),
// then compute all 128 sets from smem. DRAM traffic = 134 MB read + 67 MB
// write = 201 MB (the information-theoretic floor).

#define BB 32
#define CC 256
#define HWP 4096          // 64*64
#define SS 128
#define KK 8
#define TT 32             // hw tile width (floats)
#define NTHREADS 256

__global__ __launch_bounds__(NTHREADS)
void fmp_kernel(const float* __restrict__ x,
                const int*   __restrict__ idx,
                float*       __restrict__ out)
{
    __shared__ float sx[CC][TT];      // 32 KB: all channels for this hw strip
    __shared__ int   sidx[SS * KK];   // 4 KB: the full index table

    const int b   = blockIdx.y;
    const int hw0 = blockIdx.x * TT;
    const int t   = threadIdx.x;

    // Stage index table (1024 ints)
    #pragma unroll
    for (int i = t; i < SS * KK; i += NTHREADS)
        sidx[i] = idx[i];

    // Stage x tile: 256 channels x 32 floats = 2048 float4 loads, coalesced.
    // i -> channel c = i>>3, quad q = i&7 (8 float4 per channel row).
    const float4* xb = reinterpret_cast<const float4*>(
        x + (size_t)b * CC * HWP + hw0);
    #pragma unroll
    for (int it = 0; it < (CC * TT / 4) / NTHREADS; ++it) {
        int i = t + it * NTHREADS;
        int c = i >> 3;
        int q = i & 7;
        float4 v = xb[(size_t)c * (HWP / 4) + q];
        *reinterpret_cast<float4*>(&sx[c][q * 4]) = v;
    }
    __syncthreads();

    // Compute: warp <-> set, lane <-> hw position.
    const int lane = t & 31;
    const int warp = t >> 5;
    float* outb = out + (size_t)b * SS * HWP + hw0;

    #pragma unroll
    for (int it = 0; it < SS / (NTHREADS / 32); ++it) {
        int s = warp + it * (NTHREADS / 32);
        const int* row = &sidx[s * KK];   // broadcast reads (conflict-free)

        float m = sx[row[0]][lane];
        #pragma unroll
        for (int k = 1; k < KK; ++k)
            m = fmaxf(m, sx[row[k]][lane]);

        outb[(size_t)s * HWP + lane] = m;  // 128 B coalesced store per warp
    }
}

extern "C" void kernel_launch(void* const* d_in, const int* in_sizes, int n_in,
                              void* d_out, int out_size)
{
    const float* x   = (const float*)d_in[0];   // [32,256,64,64] f32
    const int*   idx = (const int*)d_in[1];     // [128,8] i32
    float*       out = (float*)d_out;           // [32,128,64,64] f32

    dim3 grid(HWP / TT, BB);   // (128, 32) = 4096 CTAs
    fmp_kernel<<<grid, NTHREADS>>>(x, idx, out);
}